// round 4
// baseline (speedup 1.0000x reference)
#include <cuda_runtime.h>
#include <cuda_bf16.h>
#include <math.h>

// ---------------------------------------------------------------------------
// Problem constants
// ---------------------------------------------------------------------------
#define BB    128          // batch
#define TT    384          // sequence length
#define HH    1024         // hidden
#define N3    3072         // 3*H
#define KK    1024         // K of every GEMM
#define MFULL (BB*TT)      // 49152 rows of the input-projection GEMM

#define NBLK  128          // persistent recurrence blocks (<= 148 SMs, 1/SM)
#define UPB   (HH/NBLK)    // 8 hidden units per block
#define WSTR  1028         // padded smem row stride for W (bank-conflict free)
#define HSTR  36           // padded smem row stride for h tile
#define SW_FLOATS (3*UPB*WSTR)          // 24672
#define SH_FLOATS (BB*HSTR)             // 4608
#define SMEM_BYTES ((SW_FLOATS + SH_FLOATS) * 4)   // 117120 B

// ---------------------------------------------------------------------------
// Scratch (device globals -- allocation-free per harness rules)
// ---------------------------------------------------------------------------
__device__ float g_xg [(size_t)MFULL * N3];   // 604 MB: input projections
__device__ float g_yA [(size_t)MFULL * HH];   // 201 MB: layer outputs ping
__device__ float g_yB [(size_t)MFULL * HH];   // 201 MB: layer outputs pong
__device__ float g_h0 [BB * HH];              // hidden ping
__device__ float g_h1 [BB * HH];              // hidden pong

// grid barrier state
__device__ volatile unsigned g_barA = 0;
__device__ volatile unsigned g_gen  = 0;

__device__ __forceinline__ void grid_sync(unsigned nb)
{
    __syncthreads();
    if (threadIdx.x == 0) {
        unsigned old = g_gen;
        __threadfence();                       // release prior writes
        if (atomicAdd((unsigned*)&g_barA, 1u) == nb - 1u) {
            g_barA = 0;
            __threadfence();
            atomicAdd((unsigned*)&g_gen, 1u);  // open the gate
        } else {
            while (g_gen == old) { }
        }
        __threadfence();                       // acquire
    }
    __syncthreads();
}

// ---------------------------------------------------------------------------
// GEMM: C[m,n] = bias[n] + sum_k A[m*K+k] * B[n*K+k]   (C = A * B^T)
// BM=128, BN=64, BK=16, TM=8, TN=4, 256 threads. (input projections)
// ---------------------------------------------------------------------------
__global__ __launch_bounds__(256) void gemm_abt(
    const float* __restrict__ A, const float* __restrict__ B,
    const float* __restrict__ bias, float* __restrict__ C,
    int M, int N, int K)
{
    __shared__ float As[16][128];
    __shared__ float Bs[16][64];

    const int tid = threadIdx.x;
    const int tx  = tid & 15;
    const int ty  = tid >> 4;
    const int m0  = blockIdx.y * 128;
    const int n0  = blockIdx.x * 64;

    float acc[8][4] = {};

    for (int kt = 0; kt < K; kt += 16) {
        #pragma unroll
        for (int u = 0; u < 2; ++u) {
            int i   = tid + u * 256;
            int row = i >> 2;
            int kq  = (i & 3) << 2;
            float4 v = *(const float4*)(A + (size_t)(m0 + row) * K + (kt + kq));
            As[kq + 0][row] = v.x; As[kq + 1][row] = v.y;
            As[kq + 2][row] = v.z; As[kq + 3][row] = v.w;
        }
        {
            int i   = tid;
            int row = i >> 2;
            int kq  = (i & 3) << 2;
            float4 v = *(const float4*)(B + (size_t)(n0 + row) * K + (kt + kq));
            Bs[kq + 0][row] = v.x; Bs[kq + 1][row] = v.y;
            Bs[kq + 2][row] = v.z; Bs[kq + 3][row] = v.w;
        }
        __syncthreads();

        #pragma unroll
        for (int kk = 0; kk < 16; ++kk) {
            float4 a0 = *(const float4*)&As[kk][ty * 8];
            float4 a1 = *(const float4*)&As[kk][ty * 8 + 4];
            float4 b0 = *(const float4*)&Bs[kk][tx * 4];
            float ra[8] = {a0.x, a0.y, a0.z, a0.w, a1.x, a1.y, a1.z, a1.w};
            float rb[4] = {b0.x, b0.y, b0.z, b0.w};
            #pragma unroll
            for (int i = 0; i < 8; ++i)
                #pragma unroll
                for (int j = 0; j < 4; ++j)
                    acc[i][j] += ra[i] * rb[j];
        }
        __syncthreads();
    }

    #pragma unroll
    for (int i = 0; i < 8; ++i) {
        int m = m0 + ty * 8 + i;
        int n = n0 + tx * 4;
        float4 bv = *(const float4*)(bias + n);
        float4 v = make_float4(acc[i][0] + bv.x, acc[i][1] + bv.y,
                               acc[i][2] + bv.z, acc[i][3] + bv.w);
        *(float4*)(C + (size_t)m * N + n) = v;
    }
}

// ---------------------------------------------------------------------------
// Persistent GRU recurrence for one layer pass.
// 128 blocks x 256 threads, all co-resident (1 block/SM, 117 KB dyn smem).
// Block owns 8 hidden units; keeps their 24 Whh rows (r,z,n) in smem for all
// 384 steps. Per step: h-GEMM from smem tiles -> fused gates -> h ping-pong
// -> one grid barrier.
// Thread (tx=tid&7, ty=tid>>3): unit j0+tx, batches {ty + 32*i}.
// ---------------------------------------------------------------------------
__device__ __forceinline__ float sigf(float x) { return 1.0f / (1.0f + expf(-x)); }

__global__ __launch_bounds__(256) void gru_recurrence(
    const float* __restrict__ xg, const float* __restrict__ Whh,
    const float* __restrict__ bhh, float* __restrict__ hbuf0,
    float* __restrict__ hbuf1, float* __restrict__ y)
{
    extern __shared__ float smem[];
    float* sW = smem;                 // [3*UPB][WSTR]
    float* sH = smem + SW_FLOATS;     // [BB][HSTR]

    const int tid = threadIdx.x;
    const int tx  = tid & 7;          // unit within block
    const int ty  = tid >> 3;         // batch group 0..31
    const int j0  = blockIdx.x * UPB;
    const int j   = j0 + tx;

    // Load this block's 24 Whh rows into smem (once for the whole pass)
    #pragma unroll
    for (int r = 0; r < 3 * UPB; ++r) {
        const int g = r >> 3, u = r & 7;
        const float* src = Whh + (size_t)(g * HH + j0 + u) * KK;
        for (int k4 = tid; k4 < KK / 4; k4 += 256)
            *(float4*)&sW[r * WSTR + k4 * 4] = *(const float4*)&src[k4 * 4];
    }
    const float br = bhh[j];
    const float bz = bhh[HH + j];
    const float bn = bhh[2 * HH + j];
    __syncthreads();

    const float* hin  = hbuf0;
    float*       hout = hbuf1;

    for (int t = 0; t < TT; ++t) {
        float acc[4][3] = {};

        for (int kt = 0; kt < KK; kt += 32) {
            // stage h tile [128][32] into smem
            #pragma unroll
            for (int r = 0; r < 4; ++r) {
                int i   = tid + r * 256;       // 0..1023 float4 slots
                int row = i >> 3;
                int q   = i & 7;
                *(float4*)&sH[row * HSTR + q * 4] =
                    *(const float4*)&hin[(size_t)row * KK + kt + q * 4];
            }
            __syncthreads();

            #pragma unroll
            for (int q = 0; q < 8; ++q) {
                const int kk = kt + q * 4;
                float4 wr = *(const float4*)&sW[(0 * UPB + tx) * WSTR + kk];
                float4 wz = *(const float4*)&sW[(1 * UPB + tx) * WSTR + kk];
                float4 wn = *(const float4*)&sW[(2 * UPB + tx) * WSTR + kk];
                #pragma unroll
                for (int i = 0; i < 4; ++i) {
                    float4 hv = *(const float4*)&sH[(ty + 32 * i) * HSTR + q * 4];
                    acc[i][0] += hv.x * wr.x + hv.y * wr.y + hv.z * wr.z + hv.w * wr.w;
                    acc[i][1] += hv.x * wz.x + hv.y * wz.y + hv.z * wz.z + hv.w * wz.w;
                    acc[i][2] += hv.x * wn.x + hv.y * wn.y + hv.z * wn.z + hv.w * wn.w;
                }
            }
            __syncthreads();
        }

        // fused gates + state update (thread owns unit j for 4 batches)
        #pragma unroll
        for (int i = 0; i < 4; ++i) {
            const int b = ty + 32 * i;
            const float* xgr = xg + ((size_t)b * TT + t) * N3 + j;
            float r  = sigf(xgr[0]      + acc[i][0] + br);
            float z  = sigf(xgr[HH]     + acc[i][1] + bz);
            float n  = tanhf(xgr[2*HH]  + r * (acc[i][2] + bn));
            float hp = hin[(size_t)b * HH + j];
            float hn = (1.0f - z) * n + z * hp;
            hout[(size_t)b * HH + j] = hn;
            if (y) y[((size_t)b * TT + t) * HH + j] = hn;
        }

        grid_sync(NBLK);     // publish hout before anyone reads it next step

        // ping-pong
        const float* tmp = hin; hin = hout; hout = (float*)tmp;
    }
    // TT even -> final hidden ends in hbuf0
}

// ---------------------------------------------------------------------------
// predictions[b] = dot(h[b,:], lin_W) + lin_b
// ---------------------------------------------------------------------------
__global__ __launch_bounds__(256) void final_pred(
    const float* __restrict__ h, const float* __restrict__ W,
    const float* __restrict__ bias, float* __restrict__ out)
{
    int b = blockIdx.x;
    float s = 0.f;
    for (int j = threadIdx.x; j < HH; j += 256)
        s += h[(size_t)b * HH + j] * W[j];
    #pragma unroll
    for (int o = 16; o; o >>= 1) s += __shfl_xor_sync(0xFFFFFFFFu, s, o);
    __shared__ float ws[8];
    if ((threadIdx.x & 31) == 0) ws[threadIdx.x >> 5] = s;
    __syncthreads();
    if (threadIdx.x == 0) {
        float tsum = 0.f;
        #pragma unroll
        for (int w = 0; w < 8; ++w) tsum += ws[w];
        out[b] = tsum + bias[0];
    }
}

// ---------------------------------------------------------------------------
// Launch — 13 graph nodes total (vs 3080 before: fixes the 6 MB upload
// overhead that outlived graph teardown).
// ---------------------------------------------------------------------------
extern "C" void kernel_launch(void* const* d_in, const int* in_sizes, int n_in,
                              void* d_out, int out_size)
{
    // metadata order: 0 input_seq (dead), 1 rand_input, 2 h0, 3..6 cell_* (dead),
    // 7..10 gru layer0, 11..14 gru layer1, 15 lin_W, 16 lin_b
    const float* rand_input = (const float*)d_in[1];
    const float* h0   = (const float*)d_in[2];
    const float* Wih0 = (const float*)d_in[7];
    const float* Whh0 = (const float*)d_in[8];
    const float* bih0 = (const float*)d_in[9];
    const float* bhh0 = (const float*)d_in[10];
    const float* Wih1 = (const float*)d_in[11];
    const float* Whh1 = (const float*)d_in[12];
    const float* bih1 = (const float*)d_in[13];
    const float* bhh1 = (const float*)d_in[14];
    const float* linW = (const float*)d_in[15];
    const float* linb = (const float*)d_in[16];
    float* out = (float*)d_out;

    float *xg, *yA, *yB, *h0b, *h1b;
    cudaGetSymbolAddress((void**)&xg,  g_xg);
    cudaGetSymbolAddress((void**)&yA,  g_yA);
    cudaGetSymbolAddress((void**)&yB,  g_yB);
    cudaGetSymbolAddress((void**)&h0b, g_h0);
    cudaGetSymbolAddress((void**)&h1b, g_h1);

    cudaFuncSetAttribute(gru_recurrence,
                         cudaFuncAttributeMaxDynamicSharedMemorySize, SMEM_BYTES);

    dim3 blk(256);
    dim3 grid_xg(N3 / 64, MFULL / 128);   // 48 x 384

    auto run_pass = [&](const float* x, const float* Wih, const float* bih,
                        const float* Whh, const float* bhh, float* y) {
        gemm_abt<<<grid_xg, blk>>>(x, Wih, bih, xg, MFULL, N3, KK);
        gru_recurrence<<<NBLK, blk, SMEM_BYTES>>>(xg, Whh, bhh, h0b, h1b, y);
    };

    const size_t HBYTES = (size_t)BB * HH * sizeof(float);

    // pass 1: layer0 on rand_input, h = h0[0]
    cudaMemcpyAsync(h0b, h0, HBYTES, cudaMemcpyDeviceToDevice);
    run_pass(rand_input, Wih0, bih0, Whh0, bhh0, yA);

    // pass 2: layer1 on yA, h = h0[1]
    cudaMemcpyAsync(h0b, h0 + (size_t)BB * HH, HBYTES, cudaMemcpyDeviceToDevice);
    run_pass(yA, Wih1, bih1, Whh1, bhh1, yB);

    // split+concat over T is identity -> yB feeds second run directly
    // pass 3: layer0 on yB, h = 0
    cudaMemsetAsync(h0b, 0, HBYTES);
    run_pass(yB, Wih0, bih0, Whh0, bhh0, yA);

    // pass 4: layer1 on yA, h = 0 (y not needed)
    cudaMemsetAsync(h0b, 0, HBYTES);
    run_pass(yA, Wih1, bih1, Whh1, bhh1, nullptr);

    final_pred<<<BB, blk>>>(h0b, linW, linb, out);
}